// round 3
// baseline (speedup 1.0000x reference)
#include <cuda_runtime.h>

// Problem constants (fixed by dataset): B=4, H=8, N=4096, R=D=64
#define B_     4
#define H_     8
#define N_     4096
#define R_     64
#define BH_    32
#define CH_    16       // chunks along N for the rank-reduction GEMMs
#define CROWS_ 256      // rows per chunk (N_/CH_)
#define EB_    8        // r1 element-blocks
#define NEG_BIG 3.0e38f

typedef unsigned long long ull;

// ---------------- f32x2 packed-math helpers (sm_100+ PTX only) -------------
__device__ __forceinline__ ull dup2(float x) {
    ull r;
    asm("mov.b64 %0, {%1, %2};" : "=l"(r) : "r"(__float_as_uint(x)), "r"(__float_as_uint(x)));
    return r;
}
__device__ __forceinline__ void fma2(ull& d, ull a, ull b) {
    asm("fma.rn.f32x2 %0, %1, %2, %0;" : "+l"(d) : "l"(a), "l"(b));
}
__device__ __forceinline__ void up2(ull v, float& lo, float& hi) {
    unsigned int a, b;
    asm("mov.b64 {%0, %1}, %2;" : "=r"(a), "=r"(b) : "l"(v));
    lo = __uint_as_float(a); hi = __uint_as_float(b);
}

// ---------------- device scratch (static: no allocations allowed) ----------
__device__ float g_pm[BH_*CH_*R_];                    // partial col max
__device__ float g_ps[BH_*CH_*R_];                    // partial col expsum
__device__ float g_m [BH_*R_];                        // final col max
__device__ float g_inv[BH_*R_];                       // 1 / col expsum
__device__ float g_pKV[(size_t)BH_*CH_*R_*R_];        // partial K^T V
__device__ float g_pKK[(size_t)BH_*CH_*R_*R_];        // partial K^T K
__device__ float g_pQQ[(size_t)BH_*CH_*R_*R_];        // partial Q^T Q
__device__ float g_KtV[(size_t)BH_*R_*R_];            // reduced K^T V
__device__ float g_sQp[BH_*EB_];                      // partial sum |Q^TQ - I|
__device__ float g_sKp[BH_*EB_];                      // partial sum |K^TK - I|

// ============================================================================
// KS1: per-(bh, chunk) column max and exp-sum of (svd_V + mask bias) over N
// grid (32, 16), 256 threads. tid%64 = column r, tid/64 = row group
// ============================================================================
__global__ void __launch_bounds__(256) svda_ks1(const float* __restrict__ sv,
                                                const float* __restrict__ mask) {
    const int bh = blockIdx.x, c = blockIdx.y;
    const int b  = bh >> 3;
    const int tid = threadIdx.x;
    const int r = tid & 63, g = tid >> 6;                 // g in 0..3
    const float* base = sv + ((size_t)bh * N_ + (size_t)c * CROWS_) * R_;
    const float* mk   = mask + (size_t)b * N_ + (size_t)c * CROWS_;

    __shared__ float sred[4][64];

    float m = -NEG_BIG;
    for (int i = g; i < CROWS_; i += 4) {
        float x = base[(size_t)i * R_ + r] - 1e9f * (1.0f - mk[i]);
        m = fmaxf(m, x);
    }
    sred[g][r] = m;
    __syncthreads();
    if (g == 0) {
        m = fmaxf(fmaxf(sred[0][r], sred[1][r]), fmaxf(sred[2][r], sred[3][r]));
        sred[0][r] = m;
    }
    __syncthreads();
    m = sred[0][r];
    __syncthreads();

    float s = 0.0f;
    for (int i = g; i < CROWS_; i += 4) {
        float x = base[(size_t)i * R_ + r] - 1e9f * (1.0f - mk[i]);
        s += __expf(x - m);
    }
    sred[g][r] = s;
    __syncthreads();
    if (g == 0) {
        s = sred[0][r] + sred[1][r] + sred[2][r] + sred[3][r];
        g_pm[(bh * CH_ + c) * R_ + r] = m;
        g_ps[(bh * CH_ + c) * R_ + r] = s;
    }
}

// ============================================================================
// KS2: combine chunk partials into final column max and 1/sum. grid 32, 64 thr
// ============================================================================
__global__ void svda_ks2() {
    const int bh = blockIdx.x;
    const int r  = threadIdx.x;
    float m = -NEG_BIG;
    #pragma unroll
    for (int c = 0; c < CH_; c++) m = fmaxf(m, g_pm[(bh * CH_ + c) * R_ + r]);
    float s = 0.0f;
    #pragma unroll
    for (int c = 0; c < CH_; c++)
        s += g_ps[(bh * CH_ + c) * R_ + r] * __expf(g_pm[(bh * CH_ + c) * R_ + r] - m);
    g_m[bh * R_ + r]   = m;
    g_inv[bh * R_ + r] = 1.0f / s;
}

// ============================================================================
// K2: per-(bh, chunk) partial 64x64 reductions over 256 rows:
//     K^T V, K^T K, Q^T Q.  K and Q (softmaxes) computed on the fly.
// grid (32, 16), 128 threads. 8x4 microtile per thread, f32x2 packed FMAs.
// ============================================================================
__global__ void __launch_bounds__(128) svda_k2(const float* __restrict__ U,
                                               const float* __restrict__ sv,
                                               const float* __restrict__ V,
                                               const float* __restrict__ mask) {
    const int bh = blockIdx.x, c = blockIdx.y;
    const int b  = bh >> 3;
    const int tid = threadIdx.x;
    // loader mapping: row lr (0..15), 8-col strip lc
    const int lr = tid >> 3;
    const int lc = (tid & 7) * 8;
    // compute mapping: 8-row strip (4 pairs) x 4 cols
    const int ty8 = (tid >> 4) * 8;
    const int tx4 = (tid & 15) * 4;

    __shared__ float Ksh[16][64];
    __shared__ float Qsh[16][64];
    __shared__ float Vsh[16][64];

    const size_t off = ((size_t)bh * N_ + (size_t)c * CROWS_) * R_;
    const float* Ub = U  + off;
    const float* Sb = sv + off;
    const float* Vb = V  + off;
    const float* mk = mask + (size_t)b * N_ + (size_t)c * CROWS_;

    // column-softmax stats for this thread's 8 loader columns
    const float4 mA = *(const float4*)&g_m  [bh * R_ + lc];
    const float4 mB = *(const float4*)&g_m  [bh * R_ + lc + 4];
    const float4 iA = *(const float4*)&g_inv[bh * R_ + lc];
    const float4 iB = *(const float4*)&g_inv[bh * R_ + lc + 4];

    ull aKV[4][4], aKK[4][4], aQQ[4][4];
    #pragma unroll
    for (int i = 0; i < 4; i++)
        #pragma unroll
        for (int j = 0; j < 4; j++) { aKV[i][j] = 0ull; aKK[i][j] = 0ull; aQQ[i][j] = 0ull; }

    // prefetch tile 0
    size_t pidx = (size_t)lr * R_ + lc;
    float4 u0 = *(const float4*)&Ub[pidx], u1 = *(const float4*)&Ub[pidx + 4];
    float4 s0 = *(const float4*)&Sb[pidx], s1 = *(const float4*)&Sb[pidx + 4];
    float4 v0 = *(const float4*)&Vb[pidx], v1 = *(const float4*)&Vb[pidx + 4];
    float mk0 = mk[lr];

    for (int t = 0; t < CROWS_ / 16; t++) {
        // ---- Q: row softmax over 64 (8 lanes cooperate per row) ----
        float mx = fmaxf(fmaxf(fmaxf(u0.x, u0.y), fmaxf(u0.z, u0.w)),
                         fmaxf(fmaxf(u1.x, u1.y), fmaxf(u1.z, u1.w)));
        #pragma unroll
        for (int d = 1; d < 8; d <<= 1) mx = fmaxf(mx, __shfl_xor_sync(0xffffffffu, mx, d));
        float4 e0, e1;
        e0.x = __expf(u0.x - mx); e0.y = __expf(u0.y - mx);
        e0.z = __expf(u0.z - mx); e0.w = __expf(u0.w - mx);
        e1.x = __expf(u1.x - mx); e1.y = __expf(u1.y - mx);
        e1.z = __expf(u1.z - mx); e1.w = __expf(u1.w - mx);
        float sm = e0.x + e0.y + e0.z + e0.w + e1.x + e1.y + e1.z + e1.w;
        #pragma unroll
        for (int d = 1; d < 8; d <<= 1) sm += __shfl_xor_sync(0xffffffffu, sm, d);
        const float qiv = 1.0f / sm;
        *(float4*)&Qsh[lr][lc]     = make_float4(e0.x*qiv, e0.y*qiv, e0.z*qiv, e0.w*qiv);
        *(float4*)&Qsh[lr][lc + 4] = make_float4(e1.x*qiv, e1.y*qiv, e1.z*qiv, e1.w*qiv);

        // ---- K: column softmax exp(x - m[r]) / s[r] ----
        const float bias = -1e9f * (1.0f - mk0);
        float4 k0, k1;
        k0.x = __expf(s0.x + bias - mA.x) * iA.x;
        k0.y = __expf(s0.y + bias - mA.y) * iA.y;
        k0.z = __expf(s0.z + bias - mA.z) * iA.z;
        k0.w = __expf(s0.w + bias - mA.w) * iA.w;
        k1.x = __expf(s1.x + bias - mB.x) * iB.x;
        k1.y = __expf(s1.y + bias - mB.y) * iB.y;
        k1.z = __expf(s1.z + bias - mB.z) * iB.z;
        k1.w = __expf(s1.w + bias - mB.w) * iB.w;
        *(float4*)&Ksh[lr][lc]     = k0;
        *(float4*)&Ksh[lr][lc + 4] = k1;
        *(float4*)&Vsh[lr][lc]     = v0;
        *(float4*)&Vsh[lr][lc + 4] = v1;
        __syncthreads();

        // prefetch next tile (lands during the FMA loop below)
        if (t < CROWS_ / 16 - 1) {
            pidx = (size_t)((t + 1) * 16 + lr) * R_ + lc;
            u0 = *(const float4*)&Ub[pidx]; u1 = *(const float4*)&Ub[pidx + 4];
            s0 = *(const float4*)&Sb[pidx]; s1 = *(const float4*)&Sb[pidx + 4];
            v0 = *(const float4*)&Vb[pidx]; v1 = *(const float4*)&Vb[pidx + 4];
            mk0 = mk[(t + 1) * 16 + lr];
        }

        #pragma unroll
        for (int kk = 0; kk < 16; kk++) {
            const ulonglong2 kaA = *(const ulonglong2*)&Ksh[kk][ty8];
            const ulonglong2 kaB = *(const ulonglong2*)&Ksh[kk][ty8 + 4];
            const ulonglong2 qaA = *(const ulonglong2*)&Qsh[kk][ty8];
            const ulonglong2 qaB = *(const ulonglong2*)&Qsh[kk][ty8 + 4];
            const ull ka[4] = {kaA.x, kaA.y, kaB.x, kaB.y};
            const ull qa[4] = {qaA.x, qaA.y, qaB.x, qaB.y};
            const float4 kb = *(const float4*)&Ksh[kk][tx4];
            const float4 qb = *(const float4*)&Qsh[kk][tx4];
            const float4 vb = *(const float4*)&Vsh[kk][tx4];
            const ull kbd[4] = {dup2(kb.x), dup2(kb.y), dup2(kb.z), dup2(kb.w)};
            const ull qbd[4] = {dup2(qb.x), dup2(qb.y), dup2(qb.z), dup2(qb.w)};
            const ull vbd[4] = {dup2(vb.x), dup2(vb.y), dup2(vb.z), dup2(vb.w)};
            #pragma unroll
            for (int ip = 0; ip < 4; ip++)
                #pragma unroll
                for (int j = 0; j < 4; j++) {
                    fma2(aKV[ip][j], ka[ip], vbd[j]);
                    fma2(aKK[ip][j], ka[ip], kbd[j]);
                    fma2(aQQ[ip][j], qa[ip], qbd[j]);
                }
        }
        __syncthreads();
    }

    // write partials (deterministic reduce in next kernel, no atomics)
    const size_t pbase = (size_t)(bh * CH_ + c) * R_ * R_;
    #pragma unroll
    for (int ip = 0; ip < 4; ip++) {
        float l0, h0, l1, h1, l2, h2, l3, h3;
        const size_t o0 = pbase + (size_t)(ty8 + 2*ip)     * R_ + tx4;
        const size_t o1 = pbase + (size_t)(ty8 + 2*ip + 1) * R_ + tx4;
        up2(aKV[ip][0], l0, h0); up2(aKV[ip][1], l1, h1);
        up2(aKV[ip][2], l2, h2); up2(aKV[ip][3], l3, h3);
        *(float4*)&g_pKV[o0] = make_float4(l0, l1, l2, l3);
        *(float4*)&g_pKV[o1] = make_float4(h0, h1, h2, h3);
        up2(aKK[ip][0], l0, h0); up2(aKK[ip][1], l1, h1);
        up2(aKK[ip][2], l2, h2); up2(aKK[ip][3], l3, h3);
        *(float4*)&g_pKK[o0] = make_float4(l0, l1, l2, l3);
        *(float4*)&g_pKK[o1] = make_float4(h0, h1, h2, h3);
        up2(aQQ[ip][0], l0, h0); up2(aQQ[ip][1], l1, h1);
        up2(aQQ[ip][2], l2, h2); up2(aQQ[ip][3], l3, h3);
        *(float4*)&g_pQQ[o0] = make_float4(l0, l1, l2, l3);
        *(float4*)&g_pQQ[o1] = make_float4(h0, h1, h2, h3);
    }
}

// ============================================================================
// R1: reduce chunk partials -> g_KtV; partial sums of |Q^TQ-I|, |K^TK-I|
// grid (32, 8), 128 threads — 256 blocks (was 32: the 31us occupancy hole)
// ============================================================================
__global__ void __launch_bounds__(128) svda_r1() {
    const int bh = blockIdx.x, eb = blockIdx.y;
    const int tid = threadIdx.x;
    float aQ = 0.0f, aK = 0.0f;
    #pragma unroll
    for (int ee = 0; ee < 4; ee++) {
        const int e = eb * 512 + ee * 128 + tid;
        const int i = e >> 6, j = e & 63;
        float skv = 0.0f, skk = 0.0f, sqq = 0.0f;
        #pragma unroll
        for (int cc = 0; cc < CH_; cc++) {
            const size_t o = (size_t)(bh * CH_ + cc) * R_ * R_ + e;
            skv += g_pKV[o]; skk += g_pKK[o]; sqq += g_pQQ[o];
        }
        g_KtV[(size_t)bh * R_ * R_ + e] = skv;
        const float eye = (i == j) ? 1.0f : 0.0f;
        aQ += fabsf(sqq - eye);
        aK += fabsf(skk - eye);
    }
    __shared__ float rQ[128], rK[128];
    rQ[tid] = aQ; rK[tid] = aK;
    __syncthreads();
    for (int st = 64; st > 0; st >>= 1) {
        if (tid < st) { rQ[tid] += rQ[tid + st]; rK[tid] += rK[tid + st]; }
        __syncthreads();
    }
    if (tid == 0) { g_sQp[bh * EB_ + eb] = rQ[0]; g_sKp[bh * EB_ + eb] = rK[0]; }
}

// ============================================================================
// R2: finalize ortho_loss[b]
// ============================================================================
__global__ void svda_r2(float* __restrict__ out) {
    const int tid = threadIdx.x;
    __shared__ float sm[BH_];
    if (tid < BH_) {
        float s = 0.0f;
        #pragma unroll
        for (int eb = 0; eb < EB_; eb++)
            s += g_sQp[tid * EB_ + eb] + g_sKp[tid * EB_ + eb];
        sm[tid] = s;
    }
    __syncthreads();
    if (tid < B_) {
        float s = 0.0f;
        #pragma unroll
        for (int h = 0; h < H_; h++) s += sm[tid * H_ + h];
        out[(size_t)BH_ * N_ * R_ + tid] = 0.1f * s / (float)(H_ * R_ * R_);
    }
}

// ============================================================================
// K3: X = (softmax_r(U) * graph_filter) @ KtV
// grid (32, 64), 64 threads. 8x8 microtile per thread, f32x2 packed FMAs.
// ============================================================================
__global__ void __launch_bounds__(64) svda_k3(const float* __restrict__ U,
                                              const float* __restrict__ Sigma,
                                              const float* __restrict__ gammas,
                                              int ng,
                                              float* __restrict__ X) {
    const int bh = blockIdx.x, cb = blockIdx.y;
    const int tid = threadIdx.x;

    __shared__ float QfT[64 * 68];    // transposed: [k=r][row], pitch 68
    __shared__ float Kt[64 * 64];     // KtV [r][d]
    __shared__ float filt[64];

    // graph filter: Horner(sigmoid(Sigma))
    {
        const float x  = Sigma[bh * R_ + tid];
        const float sg = 1.0f / (1.0f + __expf(-x));
        float o = gammas[ng - 1];
        for (int k = ng - 2; k >= 0; k--) o = fmaf(o, sg, gammas[k]);
        filt[tid] = o;
    }
    // load KtV tile
    #pragma unroll
    for (int e = tid * 4; e < R_ * R_; e += 256)
        *(float4*)&Kt[e] = *(const float4*)&g_KtV[(size_t)bh * R_ * R_ + e];
    __syncthreads();

    // Qf^T: thread tid owns row tid; serial softmax over 64 then scaled store
    {
        const float* ur = U + ((size_t)bh * N_ + (size_t)cb * 64 + tid) * R_;
        float u[64];
        #pragma unroll
        for (int q = 0; q < 16; q++) {
            const float4 t4 = *(const float4*)(ur + q * 4);
            u[q*4+0] = t4.x; u[q*4+1] = t4.y; u[q*4+2] = t4.z; u[q*4+3] = t4.w;
        }
        float mx = u[0];
        #pragma unroll
        for (int r = 1; r < 64; r++) mx = fmaxf(mx, u[r]);
        float sm = 0.0f;
        #pragma unroll
        for (int r = 0; r < 64; r++) { u[r] = __expf(u[r] - mx); sm += u[r]; }
        const float inv = 1.0f / sm;
        #pragma unroll
        for (int r = 0; r < 64; r++)
            QfT[r * 68 + tid] = u[r] * inv * filt[r];
    }
    __syncthreads();

    // GEMM: X[64x64] = Qf[64x64] @ Kt[64x64]; thread tile 8 rows x 8 cols
    const int ty8 = (tid >> 3) * 8;
    const int jc  = (tid & 7) * 8;
    ull acc[4][8];
    #pragma unroll
    for (int ip = 0; ip < 4; ip++)
        #pragma unroll
        for (int jj = 0; jj < 8; jj++) acc[ip][jj] = 0ull;

    #pragma unroll 4
    for (int kk = 0; kk < 64; kk++) {
        const ulonglong2 aA = *(const ulonglong2*)&QfT[kk * 68 + ty8];
        const ulonglong2 aB = *(const ulonglong2*)&QfT[kk * 68 + ty8 + 4];
        const ull a[4] = {aA.x, aA.y, aB.x, aB.y};
        const float4 b0 = *(const float4*)&Kt[kk * 64 + jc];
        const float4 b1 = *(const float4*)&Kt[kk * 64 + jc + 4];
        const ull bd[8] = {dup2(b0.x), dup2(b0.y), dup2(b0.z), dup2(b0.w),
                           dup2(b1.x), dup2(b1.y), dup2(b1.z), dup2(b1.w)};
        #pragma unroll
        for (int ip = 0; ip < 4; ip++)
            #pragma unroll
            for (int jj = 0; jj < 8; jj++)
                fma2(acc[ip][jj], a[ip], bd[jj]);
    }

    #pragma unroll
    for (int ip = 0; ip < 4; ip++) {
        float lo[8], hi[8];
        #pragma unroll
        for (int jj = 0; jj < 8; jj++) up2(acc[ip][jj], lo[jj], hi[jj]);
        const size_t ro = ((size_t)bh * N_ + (size_t)cb * 64 + ty8 + 2*ip) * R_ + jc;
        *(float4*)&X[ro]          = make_float4(lo[0], lo[1], lo[2], lo[3]);
        *(float4*)&X[ro + 4]      = make_float4(lo[4], lo[5], lo[6], lo[7]);
        *(float4*)&X[ro + R_]     = make_float4(hi[0], hi[1], hi[2], hi[3]);
        *(float4*)&X[ro + R_ + 4] = make_float4(hi[4], hi[5], hi[6], hi[7]);
    }
}

// ============================================================================
// launcher
// inputs: 0:U 1:Sigma 2:svd_V 3:V 4:mask 5:gammas ; output: X (8388608) + loss(4)
// ============================================================================
extern "C" void kernel_launch(void* const* d_in, const int* in_sizes, int n_in,
                              void* d_out, int out_size) {
    const float* U      = (const float*)d_in[0];
    const float* Sigma  = (const float*)d_in[1];
    const float* svd_V  = (const float*)d_in[2];
    const float* V      = (const float*)d_in[3];
    const float* mask   = (const float*)d_in[4];
    const float* gammas = (const float*)d_in[5];
    const int ng = in_sizes[5];
    float* out = (float*)d_out;

    svda_ks1<<<dim3(BH_, CH_), 256>>>(svd_V, mask);
    svda_ks2<<<BH_, 64>>>();
    svda_k2 <<<dim3(BH_, CH_), 128>>>(U, svd_V, V, mask);
    svda_r1 <<<dim3(BH_, EB_), 128>>>();
    svda_r2 <<<1, 32>>>(out);
    svda_k3 <<<dim3(BH_, N_ / 64), 64>>>(U, Sigma, gammas, ng, out);
}

// round 7
// speedup vs baseline: 1.0629x; 1.0629x over previous
#include <cuda_runtime.h>

// Problem constants (fixed by dataset): B=4, H=8, N=4096, R=D=64
#define B_     4
#define H_     8
#define N_     4096
#define R_     64
#define BH_    32
#define CH_    16       // chunks along N for the rank-reduction GEMMs
#define CROWS_ 256      // rows per chunk (N_/CH_)
#define EB_    8        // r1 element-blocks
#define NEG_BIG 3.0e38f

typedef unsigned long long ull;

// ---------------- f32x2 packed-math helpers (sm_100+ PTX only) -------------
__device__ __forceinline__ ull dup2(float x) {
    ull r;
    asm("mov.b64 %0, {%1, %2};" : "=l"(r) : "r"(__float_as_uint(x)), "r"(__float_as_uint(x)));
    return r;
}
__device__ __forceinline__ void fma2(ull& d, ull a, ull b) {
    asm("fma.rn.f32x2 %0, %1, %2, %0;" : "+l"(d) : "l"(a), "l"(b));
}
__device__ __forceinline__ void up2(ull v, float& lo, float& hi) {
    unsigned int a, b;
    asm("mov.b64 {%0, %1}, %2;" : "=r"(a), "=r"(b) : "l"(v));
    lo = __uint_as_float(a); hi = __uint_as_float(b);
}

// ---------------- device scratch (static: no allocations allowed) ----------
__device__ float g_pm[BH_*CH_*R_];                    // partial col max
__device__ float g_ps[BH_*CH_*R_];                    // partial col expsum
__device__ float g_m [BH_*R_];                        // final col max
__device__ float g_inv[BH_*R_];                       // 1 / col expsum
__device__ float g_pKV[(size_t)BH_*CH_*R_*R_];        // partial K^T V
__device__ float g_pKK[(size_t)BH_*CH_*R_*R_];        // partial K^T K
__device__ float g_pQQ[(size_t)BH_*CH_*R_*R_];        // partial Q^T Q
__device__ float g_KtV[(size_t)BH_*R_*R_];            // reduced K^T V
__device__ float g_sQp[BH_*EB_];                      // partial sum |Q^TQ - I|
__device__ float g_sKp[BH_*EB_];                      // partial sum |K^TK - I|

// ============================================================================
// KS1: per-(bh, chunk) column max and exp-sum of (svd_V + mask bias) over N
// ============================================================================
__global__ void __launch_bounds__(256) svda_ks1(const float* __restrict__ sv,
                                                const float* __restrict__ mask) {
    const int bh = blockIdx.x, c = blockIdx.y;
    const int b  = bh >> 3;
    const int tid = threadIdx.x;
    const int r = tid & 63, g = tid >> 6;                 // g in 0..3
    const float* base = sv + ((size_t)bh * N_ + (size_t)c * CROWS_) * R_;
    const float* mk   = mask + (size_t)b * N_ + (size_t)c * CROWS_;

    __shared__ float sred[4][64];

    float m = -NEG_BIG;
    for (int i = g; i < CROWS_; i += 4) {
        float x = base[(size_t)i * R_ + r] - 1e9f * (1.0f - mk[i]);
        m = fmaxf(m, x);
    }
    sred[g][r] = m;
    __syncthreads();
    if (g == 0) {
        m = fmaxf(fmaxf(sred[0][r], sred[1][r]), fmaxf(sred[2][r], sred[3][r]));
        sred[0][r] = m;
    }
    __syncthreads();
    m = sred[0][r];
    __syncthreads();

    float s = 0.0f;
    for (int i = g; i < CROWS_; i += 4) {
        float x = base[(size_t)i * R_ + r] - 1e9f * (1.0f - mk[i]);
        s += __expf(x - m);
    }
    sred[g][r] = s;
    __syncthreads();
    if (g == 0) {
        s = sred[0][r] + sred[1][r] + sred[2][r] + sred[3][r];
        g_pm[(bh * CH_ + c) * R_ + r] = m;
        g_ps[(bh * CH_ + c) * R_ + r] = s;
    }
}

// ============================================================================
// KS2: combine chunk partials into final column max and 1/sum
// ============================================================================
__global__ void svda_ks2() {
    const int bh = blockIdx.x;
    const int r  = threadIdx.x;
    float m = -NEG_BIG;
    #pragma unroll
    for (int c = 0; c < CH_; c++) m = fmaxf(m, g_pm[(bh * CH_ + c) * R_ + r]);
    float s = 0.0f;
    #pragma unroll
    for (int c = 0; c < CH_; c++)
        s += g_ps[(bh * CH_ + c) * R_ + r] * __expf(g_pm[(bh * CH_ + c) * R_ + r] - m);
    g_m[bh * R_ + r]   = m;
    g_inv[bh * R_ + r] = 1.0f / s;
}

// ============================================================================
// K2: per-(bh, chunk) partial 64x64 reductions over 256 rows (PROVEN R2 code)
// ============================================================================
__global__ void __launch_bounds__(128) svda_k2(const float* __restrict__ U,
                                               const float* __restrict__ sv,
                                               const float* __restrict__ V,
                                               const float* __restrict__ mask) {
    const int bh = blockIdx.x, c = blockIdx.y;
    const int b  = bh >> 3;
    const int tid = threadIdx.x;
    const int lr = tid >> 3;
    const int lc = (tid & 7) * 8;
    const int ty8 = (tid >> 4) * 8;
    const int tx4 = (tid & 15) * 4;

    __shared__ float Ksh[16][64];
    __shared__ float Qsh[16][64];
    __shared__ float Vsh[16][64];

    const size_t off = ((size_t)bh * N_ + (size_t)c * CROWS_) * R_;
    const float* Ub = U  + off;
    const float* Sb = sv + off;
    const float* Vb = V  + off;
    const float* mk = mask + (size_t)b * N_ + (size_t)c * CROWS_;

    const float4 mA = *(const float4*)&g_m  [bh * R_ + lc];
    const float4 mB = *(const float4*)&g_m  [bh * R_ + lc + 4];
    const float4 iA = *(const float4*)&g_inv[bh * R_ + lc];
    const float4 iB = *(const float4*)&g_inv[bh * R_ + lc + 4];

    ull aKV[4][4], aKK[4][4], aQQ[4][4];
    #pragma unroll
    for (int i = 0; i < 4; i++)
        #pragma unroll
        for (int j = 0; j < 4; j++) { aKV[i][j] = 0ull; aKK[i][j] = 0ull; aQQ[i][j] = 0ull; }

    size_t pidx = (size_t)lr * R_ + lc;
    float4 u0 = *(const float4*)&Ub[pidx], u1 = *(const float4*)&Ub[pidx + 4];
    float4 s0 = *(const float4*)&Sb[pidx], s1 = *(const float4*)&Sb[pidx + 4];
    float4 v0 = *(const float4*)&Vb[pidx], v1 = *(const float4*)&Vb[pidx + 4];
    float mk0 = mk[lr];

    for (int t = 0; t < CROWS_ / 16; t++) {
        float mx = fmaxf(fmaxf(fmaxf(u0.x, u0.y), fmaxf(u0.z, u0.w)),
                         fmaxf(fmaxf(u1.x, u1.y), fmaxf(u1.z, u1.w)));
        #pragma unroll
        for (int d = 1; d < 8; d <<= 1) mx = fmaxf(mx, __shfl_xor_sync(0xffffffffu, mx, d));
        float4 e0, e1;
        e0.x = __expf(u0.x - mx); e0.y = __expf(u0.y - mx);
        e0.z = __expf(u0.z - mx); e0.w = __expf(u0.w - mx);
        e1.x = __expf(u1.x - mx); e1.y = __expf(u1.y - mx);
        e1.z = __expf(u1.z - mx); e1.w = __expf(u1.w - mx);
        float sm = e0.x + e0.y + e0.z + e0.w + e1.x + e1.y + e1.z + e1.w;
        #pragma unroll
        for (int d = 1; d < 8; d <<= 1) sm += __shfl_xor_sync(0xffffffffu, sm, d);
        const float qiv = 1.0f / sm;
        *(float4*)&Qsh[lr][lc]     = make_float4(e0.x*qiv, e0.y*qiv, e0.z*qiv, e0.w*qiv);
        *(float4*)&Qsh[lr][lc + 4] = make_float4(e1.x*qiv, e1.y*qiv, e1.z*qiv, e1.w*qiv);

        const float bias = -1e9f * (1.0f - mk0);
        float4 k0, k1;
        k0.x = __expf(s0.x + bias - mA.x) * iA.x;
        k0.y = __expf(s0.y + bias - mA.y) * iA.y;
        k0.z = __expf(s0.z + bias - mA.z) * iA.z;
        k0.w = __expf(s0.w + bias - mA.w) * iA.w;
        k1.x = __expf(s1.x + bias - mB.x) * iB.x;
        k1.y = __expf(s1.y + bias - mB.y) * iB.y;
        k1.z = __expf(s1.z + bias - mB.z) * iB.z;
        k1.w = __expf(s1.w + bias - mB.w) * iB.w;
        *(float4*)&Ksh[lr][lc]     = k0;
        *(float4*)&Ksh[lr][lc + 4] = k1;
        *(float4*)&Vsh[lr][lc]     = v0;
        *(float4*)&Vsh[lr][lc + 4] = v1;
        __syncthreads();

        if (t < CROWS_ / 16 - 1) {
            pidx = (size_t)((t + 1) * 16 + lr) * R_ + lc;
            u0 = *(const float4*)&Ub[pidx]; u1 = *(const float4*)&Ub[pidx + 4];
            s0 = *(const float4*)&Sb[pidx]; s1 = *(const float4*)&Sb[pidx + 4];
            v0 = *(const float4*)&Vb[pidx]; v1 = *(const float4*)&Vb[pidx + 4];
            mk0 = mk[(t + 1) * 16 + lr];
        }

        #pragma unroll
        for (int kk = 0; kk < 16; kk++) {
            const ulonglong2 kaA = *(const ulonglong2*)&Ksh[kk][ty8];
            const ulonglong2 kaB = *(const ulonglong2*)&Ksh[kk][ty8 + 4];
            const ulonglong2 qaA = *(const ulonglong2*)&Qsh[kk][ty8];
            const ulonglong2 qaB = *(const ulonglong2*)&Qsh[kk][ty8 + 4];
            const ull ka[4] = {kaA.x, kaA.y, kaB.x, kaB.y};
            const ull qa[4] = {qaA.x, qaA.y, qaB.x, qaB.y};
            const float4 kb = *(const float4*)&Ksh[kk][tx4];
            const float4 qb = *(const float4*)&Qsh[kk][tx4];
            const float4 vb = *(const float4*)&Vsh[kk][tx4];
            const ull kbd[4] = {dup2(kb.x), dup2(kb.y), dup2(kb.z), dup2(kb.w)};
            const ull qbd[4] = {dup2(qb.x), dup2(qb.y), dup2(qb.z), dup2(qb.w)};
            const ull vbd[4] = {dup2(vb.x), dup2(vb.y), dup2(vb.z), dup2(vb.w)};
            #pragma unroll
            for (int ip = 0; ip < 4; ip++)
                #pragma unroll
                for (int j = 0; j < 4; j++) {
                    fma2(aKV[ip][j], ka[ip], vbd[j]);
                    fma2(aKK[ip][j], ka[ip], kbd[j]);
                    fma2(aQQ[ip][j], qa[ip], qbd[j]);
                }
        }
        __syncthreads();
    }

    const size_t pbase = (size_t)(bh * CH_ + c) * R_ * R_;
    #pragma unroll
    for (int ip = 0; ip < 4; ip++) {
        float l0, h0, l1, h1, l2, h2, l3, h3;
        const size_t o0 = pbase + (size_t)(ty8 + 2*ip)     * R_ + tx4;
        const size_t o1 = pbase + (size_t)(ty8 + 2*ip + 1) * R_ + tx4;
        up2(aKV[ip][0], l0, h0); up2(aKV[ip][1], l1, h1);
        up2(aKV[ip][2], l2, h2); up2(aKV[ip][3], l3, h3);
        *(float4*)&g_pKV[o0] = make_float4(l0, l1, l2, l3);
        *(float4*)&g_pKV[o1] = make_float4(h0, h1, h2, h3);
        up2(aKK[ip][0], l0, h0); up2(aKK[ip][1], l1, h1);
        up2(aKK[ip][2], l2, h2); up2(aKK[ip][3], l3, h3);
        *(float4*)&g_pKK[o0] = make_float4(l0, l1, l2, l3);
        *(float4*)&g_pKK[o1] = make_float4(h0, h1, h2, h3);
        up2(aQQ[ip][0], l0, h0); up2(aQQ[ip][1], l1, h1);
        up2(aQQ[ip][2], l2, h2); up2(aQQ[ip][3], l3, h3);
        *(float4*)&g_pQQ[o0] = make_float4(l0, l1, l2, l3);
        *(float4*)&g_pQQ[o1] = make_float4(h0, h1, h2, h3);
    }
}

// ============================================================================
// R1: reduce chunk partials -> g_KtV + |.-I| sums. Vectorized float4 loads.
// grid (32, 8), 128 threads; each thread owns 4 consecutive elements.
// ============================================================================
__global__ void __launch_bounds__(128) svda_r1() {
    const int bh = blockIdx.x, eb = blockIdx.y;
    const int tid = threadIdx.x;
    const int e = (eb * 128 + tid) * 4;
    float4 kv = make_float4(0.f,0.f,0.f,0.f), kk = kv, qq = kv;
    #pragma unroll
    for (int cc = 0; cc < CH_; cc++) {
        const size_t o = (size_t)(bh * CH_ + cc) * R_ * R_ + e;
        const float4 a = *(const float4*)&g_pKV[o];
        const float4 d = *(const float4*)&g_pKK[o];
        const float4 q = *(const float4*)&g_pQQ[o];
        kv.x += a.x; kv.y += a.y; kv.z += a.z; kv.w += a.w;
        kk.x += d.x; kk.y += d.y; kk.z += d.z; kk.w += d.w;
        qq.x += q.x; qq.y += q.y; qq.z += q.z; qq.w += q.w;
    }
    *(float4*)&g_KtV[(size_t)bh * R_ * R_ + e] = kv;
    const int i = e >> 6, j0 = e & 63;
    float dg[4] = {0.f, 0.f, 0.f, 0.f};
    if (i >= j0 && i < j0 + 4) dg[i - j0] = 1.0f;
    float aQ = fabsf(qq.x - dg[0]) + fabsf(qq.y - dg[1]) + fabsf(qq.z - dg[2]) + fabsf(qq.w - dg[3]);
    float aK = fabsf(kk.x - dg[0]) + fabsf(kk.y - dg[1]) + fabsf(kk.z - dg[2]) + fabsf(kk.w - dg[3]);

    __shared__ float rQ[128], rK[128];
    rQ[tid] = aQ; rK[tid] = aK;
    __syncthreads();
    for (int st = 64; st > 0; st >>= 1) {
        if (tid < st) { rQ[tid] += rQ[tid + st]; rK[tid] += rK[tid + st]; }
        __syncthreads();
    }
    if (tid == 0) { g_sQp[bh * EB_ + eb] = rQ[0]; g_sKp[bh * EB_ + eb] = rK[0]; }
}

// ============================================================================
// R2: finalize ortho_loss[b]
// ============================================================================
__global__ void svda_r2(float* __restrict__ out) {
    const int tid = threadIdx.x;
    __shared__ float sm[BH_];
    if (tid < BH_) {
        float s = 0.0f;
        #pragma unroll
        for (int eb = 0; eb < EB_; eb++)
            s += g_sQp[tid * EB_ + eb] + g_sKp[tid * EB_ + eb];
        sm[tid] = s;
    }
    __syncthreads();
    if (tid < B_) {
        float s = 0.0f;
        #pragma unroll
        for (int h = 0; h < H_; h++) s += sm[tid * H_ + h];
        out[(size_t)BH_ * N_ * R_ + tid] = 0.1f * s / (float)(H_ * R_ * R_);
    }
}

// ============================================================================
// K3: X = (softmax_r(U) * graph_filter) @ KtV
// grid (32, 32), 128 threads; 128 rows per block, 8x8 f32x2 microtiles.
// dyn smem: Kt[64*64] @0, QfT[64*128] @16384 (transposed [r][row]), filt @49152
// ============================================================================
#define K3SMEM_ 49408
__global__ void __launch_bounds__(128) svda_k3(const float* __restrict__ U,
                                               const float* __restrict__ Sigma,
                                               const float* __restrict__ gammas,
                                               int ng,
                                               float* __restrict__ X) {
    extern __shared__ float s3[];
    float* Kt   = s3;                 // [r][d] 64x64
    float* QfT  = s3 + 4096;          // [r][row] 64x128
    float* filt = s3 + 4096 + 8192;   // [64]

    const int bh = blockIdx.x, cb = blockIdx.y;
    const int tid = threadIdx.x;

    if (tid < 64) {
        const float x  = Sigma[bh * R_ + tid];
        const float sg = 1.0f / (1.0f + __expf(-x));
        float o = gammas[ng - 1];
        for (int k = ng - 2; k >= 0; k--) o = fmaf(o, sg, gammas[k]);
        filt[tid] = o;
    }
    #pragma unroll
    for (int e = tid * 4; e < R_ * R_; e += 512)
        *(float4*)&Kt[e] = *(const float4*)&g_KtV[(size_t)bh * R_ * R_ + e];
    __syncthreads();

    // Qf^T: thread tid owns row tid (of 128); serial softmax then scaled store
    {
        const float* ur = U + ((size_t)bh * N_ + (size_t)cb * 128 + tid) * R_;
        float u[64];
        #pragma unroll
        for (int q = 0; q < 16; q++) {
            const float4 t4 = *(const float4*)(ur + q * 4);
            u[q*4+0] = t4.x; u[q*4+1] = t4.y; u[q*4+2] = t4.z; u[q*4+3] = t4.w;
        }
        float mx = u[0];
        #pragma unroll
        for (int r = 1; r < 64; r++) mx = fmaxf(mx, u[r]);
        float sm = 0.0f;
        #pragma unroll
        for (int r = 0; r < 64; r++) { u[r] = __expf(u[r] - mx); sm += u[r]; }
        const float inv = 1.0f / sm;
        #pragma unroll
        for (int r = 0; r < 64; r++)
            QfT[r * 128 + tid] = u[r] * inv * filt[r];
    }
    __syncthreads();

    // GEMM: X[128x64] = Qf[128x64] @ Kt[64x64]; thread tile 8 rows x 8 cols
    const int ty8 = (tid >> 3) * 8;       // 16 row-groups
    const int jc  = (tid & 7) * 8;        // 8 col-groups
    ull acc[4][8];
    #pragma unroll
    for (int ip = 0; ip < 4; ip++)
        #pragma unroll
        for (int jj = 0; jj < 8; jj++) acc[ip][jj] = 0ull;

    #pragma unroll 4
    for (int kk = 0; kk < 64; kk++) {
        const ulonglong2 aA = *(const ulonglong2*)&QfT[kk * 128 + ty8];
        const ulonglong2 aB = *(const ulonglong2*)&QfT[kk * 128 + ty8 + 4];
        const ull a[4] = {aA.x, aA.y, aB.x, aB.y};
        const float4 b0 = *(const float4*)&Kt[kk * 64 + jc];
        const float4 b1 = *(const float4*)&Kt[kk * 64 + jc + 4];
        const ull bd[8] = {dup2(b0.x), dup2(b0.y), dup2(b0.z), dup2(b0.w),
                           dup2(b1.x), dup2(b1.y), dup2(b1.z), dup2(b1.w)};
        #pragma unroll
        for (int ip = 0; ip < 4; ip++)
            #pragma unroll
            for (int jj = 0; jj < 8; jj++)
                fma2(acc[ip][jj], a[ip], bd[jj]);
    }

    #pragma unroll
    for (int ip = 0; ip < 4; ip++) {
        float lo[8], hi[8];
        #pragma unroll
        for (int jj = 0; jj < 8; jj++) up2(acc[ip][jj], lo[jj], hi[jj]);
        const size_t ro = ((size_t)bh * N_ + (size_t)cb * 128 + ty8 + 2*ip) * R_ + jc;
        *(float4*)&X[ro]          = make_float4(lo[0], lo[1], lo[2], lo[3]);
        *(float4*)&X[ro + 4]      = make_float4(lo[4], lo[5], lo[6], lo[7]);
        *(float4*)&X[ro + R_]     = make_float4(hi[0], hi[1], hi[2], hi[3]);
        *(float4*)&X[ro + R_ + 4] = make_float4(hi[4], hi[5], hi[6], hi[7]);
    }
}

// ============================================================================
// launcher
// inputs: 0:U 1:Sigma 2:svd_V 3:V 4:mask 5:gammas ; output: X (8388608) + loss(4)
// ============================================================================
extern "C" void kernel_launch(void* const* d_in, const int* in_sizes, int n_in,
                              void* d_out, int out_size) {
    const float* U      = (const float*)d_in[0];
    const float* Sigma  = (const float*)d_in[1];
    const float* svd_V  = (const float*)d_in[2];
    const float* V      = (const float*)d_in[3];
    const float* mask   = (const float*)d_in[4];
    const float* gammas = (const float*)d_in[5];
    const int ng = in_sizes[5];
    float* out = (float*)d_out;

    cudaFuncSetAttribute(svda_k3, cudaFuncAttributeMaxDynamicSharedMemorySize, K3SMEM_);

    svda_ks1<<<dim3(BH_, CH_), 256>>>(svd_V, mask);
    svda_ks2<<<BH_, 64>>>();
    svda_k2 <<<dim3(BH_, CH_), 128>>>(U, svd_V, V, mask);
    svda_r1 <<<dim3(BH_, EB_), 128>>>();
    svda_r2 <<<1, 32>>>(out);
    svda_k3 <<<dim3(BH_, N_ / 128), 128, K3SMEM_>>>(U, Sigma, gammas, ng, out);
}

// round 8
// speedup vs baseline: 1.4830x; 1.3952x over previous
#include <cuda_runtime.h>
#include <cuda_bf16.h>

// Problem constants: B=4, H=8, N=4096, R=D=64
#define B_     4
#define H_     8
#define N_     4096
#define R_     64
#define BH_    32
#define KCH_   16      // ks1 chunks
#define KROWS_ 256
#define CH2_   8       // k2 chunks
#define C2ROWS_ 512
#define EB_    8
#define NEG_BIG 3.0e38f

typedef unsigned long long ull;
typedef unsigned int u32;

// ---------------- f32x2 packed helpers (k3) ---------------------------------
__device__ __forceinline__ ull dup2(float x) {
    ull r;
    asm("mov.b64 %0, {%1, %2};" : "=l"(r) : "r"(__float_as_uint(x)), "r"(__float_as_uint(x)));
    return r;
}
__device__ __forceinline__ void fma2(ull& d, ull a, ull b) {
    asm("fma.rn.f32x2 %0, %1, %2, %0;" : "+l"(d) : "l"(a), "l"(b));
}
__device__ __forceinline__ void up2(ull v, float& lo, float& hi) {
    u32 a, b;
    asm("mov.b64 {%0, %1}, %2;" : "=r"(a), "=r"(b) : "l"(v));
    lo = __uint_as_float(a); hi = __uint_as_float(b);
}

// ---------------- mma.sync helpers (works on plain sm_103) ------------------
__device__ __forceinline__ void ldmT4(u32 a, u32* r) {
    asm volatile("ldmatrix.sync.aligned.m8n8.x4.trans.shared.b16 {%0,%1,%2,%3}, [%4];"
        : "=r"(r[0]), "=r"(r[1]), "=r"(r[2]), "=r"(r[3]) : "r"(a));
}
__device__ __forceinline__ void mma16816(float* c, const u32* a, u32 b0, u32 b1) {
    asm volatile("mma.sync.aligned.m16n8k16.row.col.f32.bf16.bf16.f32 "
        "{%0,%1,%2,%3}, {%4,%5,%6,%7}, {%8,%9}, {%0,%1,%2,%3};"
        : "+f"(c[0]), "+f"(c[1]), "+f"(c[2]), "+f"(c[3])
        : "r"(a[0]), "r"(a[1]), "r"(a[2]), "r"(a[3]), "r"(b0), "r"(b1));
}
// bf16 hi/lo split of a float pair packed as u32 (lo element in low half)
__device__ __forceinline__ void split2(float x, float y, u32& hi, u32& lo) {
    __nv_bfloat162 h = __floats2bfloat162_rn(x, y);
    hi = *reinterpret_cast<u32*>(&h);
    __nv_bfloat162 l = __floats2bfloat162_rn(x - __bfloat162float(h.x),
                                             y - __bfloat162float(h.y));
    lo = *reinterpret_cast<u32*>(&l);
}

// ---------------- device scratch --------------------------------------------
__device__ float g_pm[BH_*KCH_*R_];
__device__ float g_ps[BH_*KCH_*R_];
__device__ float g_m [BH_*R_];
__device__ float g_inv[BH_*R_];
__device__ float g_pKV[(size_t)BH_*CH2_*R_*R_];
__device__ float g_pKK[(size_t)BH_*CH2_*R_*R_];
__device__ float g_pQQ[(size_t)BH_*CH2_*R_*R_];
__device__ float g_KtV[(size_t)BH_*R_*R_];
__device__ float g_sQp[BH_*EB_];
__device__ float g_sKp[BH_*EB_];

// ============================================================================
// KS1/KS2: column softmax stats for K
// ============================================================================
__global__ void __launch_bounds__(256) svda_ks1(const float* __restrict__ sv,
                                                const float* __restrict__ mask) {
    const int bh = blockIdx.x, c = blockIdx.y;
    const int b  = bh >> 3;
    const int tid = threadIdx.x;
    const int r = tid & 63, g = tid >> 6;
    const float* base = sv + ((size_t)bh * N_ + (size_t)c * KROWS_) * R_;
    const float* mk   = mask + (size_t)b * N_ + (size_t)c * KROWS_;
    __shared__ float sred[4][64];

    float m = -NEG_BIG;
    for (int i = g; i < KROWS_; i += 4) {
        float x = base[(size_t)i * R_ + r] - 1e9f * (1.0f - mk[i]);
        m = fmaxf(m, x);
    }
    sred[g][r] = m;
    __syncthreads();
    if (g == 0) {
        m = fmaxf(fmaxf(sred[0][r], sred[1][r]), fmaxf(sred[2][r], sred[3][r]));
        sred[0][r] = m;
    }
    __syncthreads();
    m = sred[0][r];
    __syncthreads();
    float s = 0.0f;
    for (int i = g; i < KROWS_; i += 4) {
        float x = base[(size_t)i * R_ + r] - 1e9f * (1.0f - mk[i]);
        s += __expf(x - m);
    }
    sred[g][r] = s;
    __syncthreads();
    if (g == 0) {
        s = sred[0][r] + sred[1][r] + sred[2][r] + sred[3][r];
        g_pm[(bh * KCH_ + c) * R_ + r] = m;
        g_ps[(bh * KCH_ + c) * R_ + r] = s;
    }
}

__global__ void svda_ks2() {
    const int bh = blockIdx.x;
    const int r  = threadIdx.x;
    float m = -NEG_BIG;
    #pragma unroll
    for (int c = 0; c < KCH_; c++) m = fmaxf(m, g_pm[(bh * KCH_ + c) * R_ + r]);
    float s = 0.0f;
    #pragma unroll
    for (int c = 0; c < KCH_; c++)
        s += g_ps[(bh * KCH_ + c) * R_ + r] * __expf(g_pm[(bh * KCH_ + c) * R_ + r] - m);
    g_m[bh * R_ + r]   = m;
    g_inv[bh * R_ + r] = 1.0f / s;
}

// ============================================================================
// K2: rank reductions K^T V, K^T K, Q^T Q on HMMA (mma.sync bf16 hi/lo split).
// grid (32, 8), 128 threads (4 warps). Warp w owns output m-rows 16w..16w+15.
// Per 16-row n-tile: stage K/Q/V bf16 hi/lo into [n][feat] smem (pitch 72),
// ldmatrix.x4.trans for A (feat x n) and B (n x feat), 72 HMMA/warp.
// ============================================================================
#define TP_ 72   // tile pitch in bf16 elements (144B: conflict-free ldmatrix)

__global__ void __launch_bounds__(128) svda_k2(const float* __restrict__ U,
                                               const float* __restrict__ sv,
                                               const float* __restrict__ V,
                                               const float* __restrict__ mask) {
    __shared__ __align__(16) unsigned short tKh[16*TP_], tKl[16*TP_];
    __shared__ __align__(16) unsigned short tQh[16*TP_], tQl[16*TP_];
    __shared__ __align__(16) unsigned short tVh[16*TP_], tVl[16*TP_];

    const int bh = blockIdx.x, c = blockIdx.y, b = bh >> 3;
    const int tid = threadIdx.x, warp = tid >> 5, lane = tid & 31;
    const int lr = tid >> 3, lc = (tid & 7) * 8;          // staging map
    const int g = lane >> 2, tg = lane & 3;               // fragment map

    const size_t off = ((size_t)bh * N_ + (size_t)c * C2ROWS_) * R_;
    const float* Ub = U  + off;
    const float* Sb = sv + off;
    const float* Vb = V  + off;
    const float* mk = mask + (size_t)b * N_ + (size_t)c * C2ROWS_;

    const float4 mA = *(const float4*)&g_m  [bh * R_ + lc];
    const float4 mB = *(const float4*)&g_m  [bh * R_ + lc + 4];
    const float4 iA = *(const float4*)&g_inv[bh * R_ + lc];
    const float4 iB = *(const float4*)&g_inv[bh * R_ + lc + 4];

    float cKV[8][4], cKK[8][4], cQQ[8][4];
    #pragma unroll
    for (int i = 0; i < 8; i++)
        #pragma unroll
        for (int j = 0; j < 4; j++) { cKV[i][j] = 0.f; cKK[i][j] = 0.f; cQQ[i][j] = 0.f; }

    // ldmatrix lane addresses (byte offsets into a tile)
    // A (m=feat x k=n): rows 0-7/8-15 x cols f0/f0+8 quadrant order a0,a1,a2,a3
    const int arow = (lane & 7) + ((lane >> 4) & 1) * 8;
    const int acol = warp * 16 + ((lane >> 3) & 1) * 8;
    const u32 aoff = (u32)(arow * TP_ + acol) * 2;
    // B (k=n x n'=feat): mats (b0,b1) for n'-block even, (b2,b3) odd
    const int brow = (lane & 7) + ((lane >> 3) & 1) * 8;
    const int bcol = ((lane >> 4) & 1) * 8;
    const u32 boff = (u32)(brow * TP_ + bcol) * 2;

    const u32 aKh = (u32)__cvta_generic_to_shared(tKh) + aoff;
    const u32 aKl = (u32)__cvta_generic_to_shared(tKl) + aoff;
    const u32 aQh = (u32)__cvta_generic_to_shared(tQh) + aoff;
    const u32 aQl = (u32)__cvta_generic_to_shared(tQl) + aoff;
    const u32 bVh = (u32)__cvta_generic_to_shared(tVh) + boff;
    const u32 bVl = (u32)__cvta_generic_to_shared(tVl) + boff;
    const u32 bKh = (u32)__cvta_generic_to_shared(tKh) + boff;
    const u32 bKl = (u32)__cvta_generic_to_shared(tKl) + boff;
    const u32 bQh = (u32)__cvta_generic_to_shared(tQh) + boff;
    const u32 bQl = (u32)__cvta_generic_to_shared(tQl) + boff;

    // prefetch tile 0
    size_t pidx = (size_t)lr * R_ + lc;
    float4 u0 = *(const float4*)&Ub[pidx], u1 = *(const float4*)&Ub[pidx + 4];
    float4 s0 = *(const float4*)&Sb[pidx], s1 = *(const float4*)&Sb[pidx + 4];
    float4 v0 = *(const float4*)&Vb[pidx], v1 = *(const float4*)&Vb[pidx + 4];
    float mk0 = mk[lr];

    for (int t = 0; t < C2ROWS_ / 16; t++) {
        // ---- staging: Q row softmax, K column softmax, split to bf16 tiles --
        float mx = fmaxf(fmaxf(fmaxf(u0.x, u0.y), fmaxf(u0.z, u0.w)),
                         fmaxf(fmaxf(u1.x, u1.y), fmaxf(u1.z, u1.w)));
        #pragma unroll
        for (int d = 1; d < 8; d <<= 1) mx = fmaxf(mx, __shfl_xor_sync(0xffffffffu, mx, d));
        float q0 = __expf(u0.x - mx), q1 = __expf(u0.y - mx);
        float q2 = __expf(u0.z - mx), q3 = __expf(u0.w - mx);
        float q4 = __expf(u1.x - mx), q5 = __expf(u1.y - mx);
        float q6 = __expf(u1.z - mx), q7 = __expf(u1.w - mx);
        float sm = q0 + q1 + q2 + q3 + q4 + q5 + q6 + q7;
        #pragma unroll
        for (int d = 1; d < 8; d <<= 1) sm += __shfl_xor_sync(0xffffffffu, sm, d);
        const float qiv = 1.0f / sm;
        q0 *= qiv; q1 *= qiv; q2 *= qiv; q3 *= qiv;
        q4 *= qiv; q5 *= qiv; q6 *= qiv; q7 *= qiv;

        const float bias = -1e9f * (1.0f - mk0);
        const float k0 = __expf(s0.x + bias - mA.x) * iA.x;
        const float k1 = __expf(s0.y + bias - mA.y) * iA.y;
        const float k2 = __expf(s0.z + bias - mA.z) * iA.z;
        const float k3 = __expf(s0.w + bias - mA.w) * iA.w;
        const float k4 = __expf(s1.x + bias - mB.x) * iB.x;
        const float k5 = __expf(s1.y + bias - mB.y) * iB.y;
        const float k6 = __expf(s1.z + bias - mB.z) * iB.z;
        const float k7 = __expf(s1.w + bias - mB.w) * iB.w;

        u32 h0, h1, h2, h3, l0, l1, l2, l3;
        const int so = lr * TP_ + lc;
        split2(q0, q1, h0, l0); split2(q2, q3, h1, l1);
        split2(q4, q5, h2, l2); split2(q6, q7, h3, l3);
        *(uint4*)&tQh[so] = make_uint4(h0, h1, h2, h3);
        *(uint4*)&tQl[so] = make_uint4(l0, l1, l2, l3);
        split2(k0, k1, h0, l0); split2(k2, k3, h1, l1);
        split2(k4, k5, h2, l2); split2(k6, k7, h3, l3);
        *(uint4*)&tKh[so] = make_uint4(h0, h1, h2, h3);
        *(uint4*)&tKl[so] = make_uint4(l0, l1, l2, l3);
        split2(v0.x, v0.y, h0, l0); split2(v0.z, v0.w, h1, l1);
        split2(v1.x, v1.y, h2, l2); split2(v1.z, v1.w, h3, l3);
        *(uint4*)&tVh[so] = make_uint4(h0, h1, h2, h3);
        *(uint4*)&tVl[so] = make_uint4(l0, l1, l2, l3);
        __syncthreads();

        // prefetch next tile during MMA
        if (t < C2ROWS_ / 16 - 1) {
            pidx = (size_t)((t + 1) * 16 + lr) * R_ + lc;
            u0 = *(const float4*)&Ub[pidx]; u1 = *(const float4*)&Ub[pidx + 4];
            s0 = *(const float4*)&Sb[pidx]; s1 = *(const float4*)&Sb[pidx + 4];
            v0 = *(const float4*)&Vb[pidx]; v1 = *(const float4*)&Vb[pidx + 4];
            mk0 = mk[(t + 1) * 16 + lr];
        }

        // ---- A fragments for this warp's m-strip ----
        u32 fKh[4], fKl[4], fQh[4], fQl[4];
        ldmT4(aKh, fKh); ldmT4(aKl, fKl); ldmT4(aQh, fQh); ldmT4(aQl, fQl);

        // ---- B fragments + MMA over 4 n'-pair-blocks ----
        #pragma unroll
        for (int nb = 0; nb < 4; nb++) {
            const u32 nof = (u32)nb * 32;      // 16 feats * 2 bytes
            u32 bh4[4], bl4[4];
            // V (for K^T V)
            ldmT4(bVh + nof, bh4); ldmT4(bVl + nof, bl4);
            mma16816(cKV[2*nb],   fKh, bh4[0], bh4[1]);
            mma16816(cKV[2*nb+1], fKh, bh4[2], bh4[3]);
            mma16816(cKV[2*nb],   fKl, bh4[0], bh4[1]);
            mma16816(cKV[2*nb+1], fKl, bh4[2], bh4[3]);
            mma16816(cKV[2*nb],   fKh, bl4[0], bl4[1]);
            mma16816(cKV[2*nb+1], fKh, bl4[2], bl4[3]);
            // K (for K^T K)
            ldmT4(bKh + nof, bh4); ldmT4(bKl + nof, bl4);
            mma16816(cKK[2*nb],   fKh, bh4[0], bh4[1]);
            mma16816(cKK[2*nb+1], fKh, bh4[2], bh4[3]);
            mma16816(cKK[2*nb],   fKl, bh4[0], bh4[1]);
            mma16816(cKK[2*nb+1], fKl, bh4[2], bh4[3]);
            mma16816(cKK[2*nb],   fKh, bl4[0], bl4[1]);
            mma16816(cKK[2*nb+1], fKh, bl4[2], bl4[3]);
            // Q (for Q^T Q)
            ldmT4(bQh + nof, bh4); ldmT4(bQl + nof, bl4);
            mma16816(cQQ[2*nb],   fQh, bh4[0], bh4[1]);
            mma16816(cQQ[2*nb+1], fQh, bh4[2], bh4[3]);
            mma16816(cQQ[2*nb],   fQl, bh4[0], bh4[1]);
            mma16816(cQQ[2*nb+1], fQl, bh4[2], bh4[3]);
            mma16816(cQQ[2*nb],   fQh, bl4[0], bl4[1]);
            mma16816(cQQ[2*nb+1], fQh, bl4[2], bl4[3]);
        }
        __syncthreads();
    }

    // ---- epilogue: write partials ----
    const size_t pb = (size_t)(bh * CH2_ + c) * R_ * R_;
    const int m0 = warp * 16 + g;
    #pragma unroll
    for (int nb = 0; nb < 8; nb++) {
        const int col = nb * 8 + tg * 2;
        *(float2*)&g_pKV[pb + (size_t)m0 * 64 + col]       = make_float2(cKV[nb][0], cKV[nb][1]);
        *(float2*)&g_pKV[pb + (size_t)(m0 + 8) * 64 + col] = make_float2(cKV[nb][2], cKV[nb][3]);
        *(float2*)&g_pKK[pb + (size_t)m0 * 64 + col]       = make_float2(cKK[nb][0], cKK[nb][1]);
        *(float2*)&g_pKK[pb + (size_t)(m0 + 8) * 64 + col] = make_float2(cKK[nb][2], cKK[nb][3]);
        *(float2*)&g_pQQ[pb + (size_t)m0 * 64 + col]       = make_float2(cQQ[nb][0], cQQ[nb][1]);
        *(float2*)&g_pQQ[pb + (size_t)(m0 + 8) * 64 + col] = make_float2(cQQ[nb][2], cQQ[nb][3]);
    }
}

// ============================================================================
// R1: reduce chunk partials (vectorized). grid (32, 8), 128 threads.
// ============================================================================
__global__ void __launch_bounds__(128) svda_r1() {
    const int bh = blockIdx.x, eb = blockIdx.y;
    const int tid = threadIdx.x;
    const int e = (eb * 128 + tid) * 4;
    float4 kv = make_float4(0.f,0.f,0.f,0.f), kk = kv, qq = kv;
    #pragma unroll
    for (int cc = 0; cc < CH2_; cc++) {
        const size_t o = (size_t)(bh * CH2_ + cc) * R_ * R_ + e;
        const float4 a = *(const float4*)&g_pKV[o];
        const float4 d = *(const float4*)&g_pKK[o];
        const float4 q = *(const float4*)&g_pQQ[o];
        kv.x += a.x; kv.y += a.y; kv.z += a.z; kv.w += a.w;
        kk.x += d.x; kk.y += d.y; kk.z += d.z; kk.w += d.w;
        qq.x += q.x; qq.y += q.y; qq.z += q.z; qq.w += q.w;
    }
    *(float4*)&g_KtV[(size_t)bh * R_ * R_ + e] = kv;
    const int i = e >> 6, j0 = e & 63;
    float dg[4] = {0.f, 0.f, 0.f, 0.f};
    if (i >= j0 && i < j0 + 4) dg[i - j0] = 1.0f;
    float aQ = fabsf(qq.x - dg[0]) + fabsf(qq.y - dg[1]) + fabsf(qq.z - dg[2]) + fabsf(qq.w - dg[3]);
    float aK = fabsf(kk.x - dg[0]) + fabsf(kk.y - dg[1]) + fabsf(kk.z - dg[2]) + fabsf(kk.w - dg[3]);

    __shared__ float rQ[128], rK[128];
    rQ[tid] = aQ; rK[tid] = aK;
    __syncthreads();
    for (int st = 64; st > 0; st >>= 1) {
        if (tid < st) { rQ[tid] += rQ[tid + st]; rK[tid] += rK[tid + st]; }
        __syncthreads();
    }
    if (tid == 0) { g_sQp[bh * EB_ + eb] = rQ[0]; g_sKp[bh * EB_ + eb] = rK[0]; }
}

// ============================================================================
// R2: finalize ortho_loss[b]
// ============================================================================
__global__ void svda_r2(float* __restrict__ out) {
    const int tid = threadIdx.x;
    __shared__ float sm[BH_];
    if (tid < BH_) {
        float s = 0.0f;
        #pragma unroll
        for (int eb = 0; eb < EB_; eb++)
            s += g_sQp[tid * EB_ + eb] + g_sKp[tid * EB_ + eb];
        sm[tid] = s;
    }
    __syncthreads();
    if (tid < B_) {
        float s = 0.0f;
        #pragma unroll
        for (int h = 0; h < H_; h++) s += sm[tid * H_ + h];
        out[(size_t)BH_ * N_ * R_ + tid] = 0.1f * s / (float)(H_ * R_ * R_);
    }
}

// ============================================================================
// K3: X = (softmax_r(U) * graph_filter) @ KtV  (proven R7 version)
// ============================================================================
#define K3SMEM_ 49408
__global__ void __launch_bounds__(128) svda_k3(const float* __restrict__ U,
                                               const float* __restrict__ Sigma,
                                               const float* __restrict__ gammas,
                                               int ng,
                                               float* __restrict__ X) {
    extern __shared__ float s3[];
    float* Kt   = s3;
    float* QfT  = s3 + 4096;
    float* filt = s3 + 4096 + 8192;

    const int bh = blockIdx.x, cb = blockIdx.y;
    const int tid = threadIdx.x;

    if (tid < 64) {
        const float x  = Sigma[bh * R_ + tid];
        const float sg = 1.0f / (1.0f + __expf(-x));
        float o = gammas[ng - 1];
        for (int k = ng - 2; k >= 0; k--) o = fmaf(o, sg, gammas[k]);
        filt[tid] = o;
    }
    #pragma unroll
    for (int e = tid * 4; e < R_ * R_; e += 512)
        *(float4*)&Kt[e] = *(const float4*)&g_KtV[(size_t)bh * R_ * R_ + e];
    __syncthreads();

    {
        const float* ur = U + ((size_t)bh * N_ + (size_t)cb * 128 + tid) * R_;
        float u[64];
        #pragma unroll
        for (int q = 0; q < 16; q++) {
            const float4 t4 = *(const float4*)(ur + q * 4);
            u[q*4+0] = t4.x; u[q*4+1] = t4.y; u[q*4+2] = t4.z; u[q*4+3] = t4.w;
        }
        float mx = u[0];
        #pragma unroll
        for (int r = 1; r < 64; r++) mx = fmaxf(mx, u[r]);
        float sm = 0.0f;
        #pragma unroll
        for (int r = 0; r < 64; r++) { u[r] = __expf(u[r] - mx); sm += u[r]; }
        const float inv = 1.0f / sm;
        #pragma unroll
        for (int r = 0; r < 64; r++)
            QfT[r * 128 + tid] = u[r] * inv * filt[r];
    }
    __syncthreads();

    const int ty8 = (tid >> 3) * 8;
    const int jc  = (tid & 7) * 8;
    ull acc[4][8];
    #pragma unroll
    for (int ip = 0; ip < 4; ip++)
        #pragma unroll
        for (int jj = 0; jj < 8; jj++) acc[ip][jj] = 0ull;

    #pragma unroll 4
    for (int kk = 0; kk < 64; kk++) {
        const ulonglong2 aA = *(const ulonglong2*)&QfT[kk * 128 + ty8];
        const ulonglong2 aB = *(const ulonglong2*)&QfT[kk * 128 + ty8 + 4];
        const ull a[4] = {aA.x, aA.y, aB.x, aB.y};
        const float4 b0 = *(const float4*)&Kt[kk * 64 + jc];
        const float4 b1 = *(const float4*)&Kt[kk * 64 + jc + 4];
        const ull bd[8] = {dup2(b0.x), dup2(b0.y), dup2(b0.z), dup2(b0.w),
                           dup2(b1.x), dup2(b1.y), dup2(b1.z), dup2(b1.w)};
        #pragma unroll
        for (int ip = 0; ip < 4; ip++)
            #pragma unroll
            for (int jj = 0; jj < 8; jj++)
                fma2(acc[ip][jj], a[ip], bd[jj]);
    }

    #pragma unroll
    for (int ip = 0; ip < 4; ip++) {
        float lo[8], hi[8];
        #pragma unroll
        for (int jj = 0; jj < 8; jj++) up2(acc[ip][jj], lo[jj], hi[jj]);
        const size_t ro = ((size_t)bh * N_ + (size_t)cb * 128 + ty8 + 2*ip) * R_ + jc;
        *(float4*)&X[ro]          = make_float4(lo[0], lo[1], lo[2], lo[3]);
        *(float4*)&X[ro + 4]      = make_float4(lo[4], lo[5], lo[6], lo[7]);
        *(float4*)&X[ro + R_]     = make_float4(hi[0], hi[1], hi[2], hi[3]);
        *(float4*)&X[ro + R_ + 4] = make_float4(hi[4], hi[5], hi[6], hi[7]);
    }
}

// ============================================================================
// launcher
// ============================================================================
extern "C" void kernel_launch(void* const* d_in, const int* in_sizes, int n_in,
                              void* d_out, int out_size) {
    const float* U      = (const float*)d_in[0];
    const float* Sigma  = (const float*)d_in[1];
    const float* svd_V  = (const float*)d_in[2];
    const float* V      = (const float*)d_in[3];
    const float* mask   = (const float*)d_in[4];
    const float* gammas = (const float*)d_in[5];
    const int ng = in_sizes[5];
    float* out = (float*)d_out;

    cudaFuncSetAttribute(svda_k3, cudaFuncAttributeMaxDynamicSharedMemorySize, K3SMEM_);

    svda_ks1<<<dim3(BH_, KCH_), 256>>>(svd_V, mask);
    svda_ks2<<<BH_, 64>>>();
    svda_k2 <<<dim3(BH_, CH2_), 128>>>(U, svd_V, V, mask);
    svda_r1 <<<dim3(BH_, EB_), 128>>>();
    svda_r2 <<<1, 32>>>(out);
    svda_k3 <<<dim3(BH_, N_ / 128), 128, K3SMEM_>>>(U, Sigma, gammas, ng, out);
}

// round 9
// speedup vs baseline: 1.5919x; 1.0734x over previous
#include <cuda_runtime.h>
#include <cuda_bf16.h>

// Problem constants: B=4, H=8, N=4096, R=D=64
#define B_     4
#define H_     8
#define N_     4096
#define R_     64
#define BH_    32
#define KCH_   16      // ks1 chunks
#define KROWS_ 256
#define CH2_   8       // k2 chunks
#define C2ROWS_ 512
#define EB_    16
#define NEG_BIG 3.0e38f

typedef unsigned long long ull;
typedef unsigned int u32;

// ---------------- mma.sync helpers (plain sm_103, no 'a' features) ----------
__device__ __forceinline__ void ldmT4(u32 a, u32* r) {
    asm volatile("ldmatrix.sync.aligned.m8n8.x4.trans.shared.b16 {%0,%1,%2,%3}, [%4];"
        : "=r"(r[0]), "=r"(r[1]), "=r"(r[2]), "=r"(r[3]) : "r"(a));
}
__device__ __forceinline__ void ldm4(u32 a, u32* r) {
    asm volatile("ldmatrix.sync.aligned.m8n8.x4.shared.b16 {%0,%1,%2,%3}, [%4];"
        : "=r"(r[0]), "=r"(r[1]), "=r"(r[2]), "=r"(r[3]) : "r"(a));
}
__device__ __forceinline__ void mma16816(float* c, const u32* a, u32 b0, u32 b1) {
    asm volatile("mma.sync.aligned.m16n8k16.row.col.f32.bf16.bf16.f32 "
        "{%0,%1,%2,%3}, {%4,%5,%6,%7}, {%8,%9}, {%0,%1,%2,%3};"
        : "+f"(c[0]), "+f"(c[1]), "+f"(c[2]), "+f"(c[3])
        : "r"(a[0]), "r"(a[1]), "r"(a[2]), "r"(a[3]), "r"(b0), "r"(b1));
}
// bf16 hi/lo split of a float pair packed as u32 (x in low half)
__device__ __forceinline__ void split2(float x, float y, u32& hi, u32& lo) {
    __nv_bfloat162 h = __floats2bfloat162_rn(x, y);
    hi = *reinterpret_cast<u32*>(&h);
    __nv_bfloat162 l = __floats2bfloat162_rn(x - __bfloat162float(h.x),
                                             y - __bfloat162float(h.y));
    lo = *reinterpret_cast<u32*>(&l);
}

// ---------------- device scratch --------------------------------------------
__device__ float g_pm[BH_*KCH_*R_];
__device__ float g_ps[BH_*KCH_*R_];
__device__ float g_m [BH_*R_];
__device__ float g_inv[BH_*R_];
__device__ float g_pKV[(size_t)BH_*CH2_*R_*R_];
__device__ float g_pKK[(size_t)BH_*CH2_*R_*R_];
__device__ float g_pQQ[(size_t)BH_*CH2_*R_*R_];
__device__ float g_KtV[(size_t)BH_*R_*R_];
__device__ float g_sQp[BH_*EB_];
__device__ float g_sKp[BH_*EB_];

// ============================================================================
// KS1/KS2: column softmax stats for K  (unchanged, proven)
// ============================================================================
__global__ void __launch_bounds__(256) svda_ks1(const float* __restrict__ sv,
                                                const float* __restrict__ mask) {
    const int bh = blockIdx.x, c = blockIdx.y;
    const int b  = bh >> 3;
    const int tid = threadIdx.x;
    const int r = tid & 63, g = tid >> 6;
    const float* base = sv + ((size_t)bh * N_ + (size_t)c * KROWS_) * R_;
    const float* mk   = mask + (size_t)b * N_ + (size_t)c * KROWS_;
    __shared__ float sred[4][64];

    float m = -NEG_BIG;
    for (int i = g; i < KROWS_; i += 4) {
        float x = base[(size_t)i * R_ + r] - 1e9f * (1.0f - mk[i]);
        m = fmaxf(m, x);
    }
    sred[g][r] = m;
    __syncthreads();
    if (g == 0) {
        m = fmaxf(fmaxf(sred[0][r], sred[1][r]), fmaxf(sred[2][r], sred[3][r]));
        sred[0][r] = m;
    }
    __syncthreads();
    m = sred[0][r];
    __syncthreads();
    float s = 0.0f;
    for (int i = g; i < KROWS_; i += 4) {
        float x = base[(size_t)i * R_ + r] - 1e9f * (1.0f - mk[i]);
        s += __expf(x - m);
    }
    sred[g][r] = s;
    __syncthreads();
    if (g == 0) {
        s = sred[0][r] + sred[1][r] + sred[2][r] + sred[3][r];
        g_pm[(bh * KCH_ + c) * R_ + r] = m;
        g_ps[(bh * KCH_ + c) * R_ + r] = s;
    }
}

__global__ void svda_ks2() {
    const int bh = blockIdx.x;
    const int r  = threadIdx.x;
    float m = -NEG_BIG;
    #pragma unroll
    for (int c = 0; c < KCH_; c++) m = fmaxf(m, g_pm[(bh * KCH_ + c) * R_ + r]);
    float s = 0.0f;
    #pragma unroll
    for (int c = 0; c < KCH_; c++)
        s += g_ps[(bh * KCH_ + c) * R_ + r] * __expf(g_pm[(bh * KCH_ + c) * R_ + r] - m);
    g_m[bh * R_ + r]   = m;
    g_inv[bh * R_ + r] = 1.0f / s;
}

// ============================================================================
// K2: rank reductions on HMMA (unchanged, proven in R8)
// ============================================================================
#define TP_ 72

__global__ void __launch_bounds__(128) svda_k2(const float* __restrict__ U,
                                               const float* __restrict__ sv,
                                               const float* __restrict__ V,
                                               const float* __restrict__ mask) {
    __shared__ __align__(16) unsigned short tKh[16*TP_], tKl[16*TP_];
    __shared__ __align__(16) unsigned short tQh[16*TP_], tQl[16*TP_];
    __shared__ __align__(16) unsigned short tVh[16*TP_], tVl[16*TP_];

    const int bh = blockIdx.x, c = blockIdx.y, b = bh >> 3;
    const int tid = threadIdx.x, warp = tid >> 5, lane = tid & 31;
    const int lr = tid >> 3, lc = (tid & 7) * 8;
    const int g = lane >> 2, tg = lane & 3;

    const size_t off = ((size_t)bh * N_ + (size_t)c * C2ROWS_) * R_;
    const float* Ub = U  + off;
    const float* Sb = sv + off;
    const float* Vb = V  + off;
    const float* mk = mask + (size_t)b * N_ + (size_t)c * C2ROWS_;

    const float4 mA = *(const float4*)&g_m  [bh * R_ + lc];
    const float4 mB = *(const float4*)&g_m  [bh * R_ + lc + 4];
    const float4 iA = *(const float4*)&g_inv[bh * R_ + lc];
    const float4 iB = *(const float4*)&g_inv[bh * R_ + lc + 4];

    float cKV[8][4], cKK[8][4], cQQ[8][4];
    #pragma unroll
    for (int i = 0; i < 8; i++)
        #pragma unroll
        for (int j = 0; j < 4; j++) { cKV[i][j] = 0.f; cKK[i][j] = 0.f; cQQ[i][j] = 0.f; }

    const int arow = (lane & 7) + ((lane >> 4) & 1) * 8;
    const int acol = warp * 16 + ((lane >> 3) & 1) * 8;
    const u32 aoff = (u32)(arow * TP_ + acol) * 2;
    const int brow = (lane & 7) + ((lane >> 3) & 1) * 8;
    const int bcol = ((lane >> 4) & 1) * 8;
    const u32 boff = (u32)(brow * TP_ + bcol) * 2;

    const u32 aKh = (u32)__cvta_generic_to_shared(tKh) + aoff;
    const u32 aKl = (u32)__cvta_generic_to_shared(tKl) + aoff;
    const u32 aQh = (u32)__cvta_generic_to_shared(tQh) + aoff;
    const u32 aQl = (u32)__cvta_generic_to_shared(tQl) + aoff;
    const u32 bVh = (u32)__cvta_generic_to_shared(tVh) + boff;
    const u32 bVl = (u32)__cvta_generic_to_shared(tVl) + boff;
    const u32 bKh = (u32)__cvta_generic_to_shared(tKh) + boff;
    const u32 bKl = (u32)__cvta_generic_to_shared(tKl) + boff;
    const u32 bQh = (u32)__cvta_generic_to_shared(tQh) + boff;
    const u32 bQl = (u32)__cvta_generic_to_shared(tQl) + boff;

    size_t pidx = (size_t)lr * R_ + lc;
    float4 u0 = *(const float4*)&Ub[pidx], u1 = *(const float4*)&Ub[pidx + 4];
    float4 s0 = *(const float4*)&Sb[pidx], s1 = *(const float4*)&Sb[pidx + 4];
    float4 v0 = *(const float4*)&Vb[pidx], v1 = *(const float4*)&Vb[pidx + 4];
    float mk0 = mk[lr];

    for (int t = 0; t < C2ROWS_ / 16; t++) {
        float mx = fmaxf(fmaxf(fmaxf(u0.x, u0.y), fmaxf(u0.z, u0.w)),
                         fmaxf(fmaxf(u1.x, u1.y), fmaxf(u1.z, u1.w)));
        #pragma unroll
        for (int d = 1; d < 8; d <<= 1) mx = fmaxf(mx, __shfl_xor_sync(0xffffffffu, mx, d));
        float q0 = __expf(u0.x - mx), q1 = __expf(u0.y - mx);
        float q2 = __expf(u0.z - mx), q3 = __expf(u0.w - mx);
        float q4 = __expf(u1.x - mx), q5 = __expf(u1.y - mx);
        float q6 = __expf(u1.z - mx), q7 = __expf(u1.w - mx);
        float sm = q0 + q1 + q2 + q3 + q4 + q5 + q6 + q7;
        #pragma unroll
        for (int d = 1; d < 8; d <<= 1) sm += __shfl_xor_sync(0xffffffffu, sm, d);
        const float qiv = 1.0f / sm;
        q0 *= qiv; q1 *= qiv; q2 *= qiv; q3 *= qiv;
        q4 *= qiv; q5 *= qiv; q6 *= qiv; q7 *= qiv;

        const float bias = -1e9f * (1.0f - mk0);
        const float k0 = __expf(s0.x + bias - mA.x) * iA.x;
        const float k1 = __expf(s0.y + bias - mA.y) * iA.y;
        const float k2 = __expf(s0.z + bias - mA.z) * iA.z;
        const float k3 = __expf(s0.w + bias - mA.w) * iA.w;
        const float k4 = __expf(s1.x + bias - mB.x) * iB.x;
        const float k5 = __expf(s1.y + bias - mB.y) * iB.y;
        const float k6 = __expf(s1.z + bias - mB.z) * iB.z;
        const float k7 = __expf(s1.w + bias - mB.w) * iB.w;

        u32 h0, h1, h2, h3, l0, l1, l2, l3;
        const int so = lr * TP_ + lc;
        split2(q0, q1, h0, l0); split2(q2, q3, h1, l1);
        split2(q4, q5, h2, l2); split2(q6, q7, h3, l3);
        *(uint4*)&tQh[so] = make_uint4(h0, h1, h2, h3);
        *(uint4*)&tQl[so] = make_uint4(l0, l1, l2, l3);
        split2(k0, k1, h0, l0); split2(k2, k3, h1, l1);
        split2(k4, k5, h2, l2); split2(k6, k7, h3, l3);
        *(uint4*)&tKh[so] = make_uint4(h0, h1, h2, h3);
        *(uint4*)&tKl[so] = make_uint4(l0, l1, l2, l3);
        split2(v0.x, v0.y, h0, l0); split2(v0.z, v0.w, h1, l1);
        split2(v1.x, v1.y, h2, l2); split2(v1.z, v1.w, h3, l3);
        *(uint4*)&tVh[so] = make_uint4(h0, h1, h2, h3);
        *(uint4*)&tVl[so] = make_uint4(l0, l1, l2, l3);
        __syncthreads();

        if (t < C2ROWS_ / 16 - 1) {
            pidx = (size_t)((t + 1) * 16 + lr) * R_ + lc;
            u0 = *(const float4*)&Ub[pidx]; u1 = *(const float4*)&Ub[pidx + 4];
            s0 = *(const float4*)&Sb[pidx]; s1 = *(const float4*)&Sb[pidx + 4];
            v0 = *(const float4*)&Vb[pidx]; v1 = *(const float4*)&Vb[pidx + 4];
            mk0 = mk[(t + 1) * 16 + lr];
        }

        u32 fKh[4], fKl[4], fQh[4], fQl[4];
        ldmT4(aKh, fKh); ldmT4(aKl, fKl); ldmT4(aQh, fQh); ldmT4(aQl, fQl);

        #pragma unroll
        for (int nb = 0; nb < 4; nb++) {
            const u32 nof = (u32)nb * 32;
            u32 bh4[4], bl4[4];
            ldmT4(bVh + nof, bh4); ldmT4(bVl + nof, bl4);
            mma16816(cKV[2*nb],   fKh, bh4[0], bh4[1]);
            mma16816(cKV[2*nb+1], fKh, bh4[2], bh4[3]);
            mma16816(cKV[2*nb],   fKl, bh4[0], bh4[1]);
            mma16816(cKV[2*nb+1], fKl, bh4[2], bh4[3]);
            mma16816(cKV[2*nb],   fKh, bl4[0], bl4[1]);
            mma16816(cKV[2*nb+1], fKh, bl4[2], bl4[3]);
            ldmT4(bKh + nof, bh4); ldmT4(bKl + nof, bl4);
            mma16816(cKK[2*nb],   fKh, bh4[0], bh4[1]);
            mma16816(cKK[2*nb+1], fKh, bh4[2], bh4[3]);
            mma16816(cKK[2*nb],   fKl, bh4[0], bh4[1]);
            mma16816(cKK[2*nb+1], fKl, bh4[2], bh4[3]);
            mma16816(cKK[2*nb],   fKh, bl4[0], bl4[1]);
            mma16816(cKK[2*nb+1], fKh, bl4[2], bl4[3]);
            ldmT4(bQh + nof, bh4); ldmT4(bQl + nof, bl4);
            mma16816(cQQ[2*nb],   fQh, bh4[0], bh4[1]);
            mma16816(cQQ[2*nb+1], fQh, bh4[2], bh4[3]);
            mma16816(cQQ[2*nb],   fQl, bh4[0], bh4[1]);
            mma16816(cQQ[2*nb+1], fQl, bh4[2], bh4[3]);
            mma16816(cQQ[2*nb],   fQh, bl4[0], bl4[1]);
            mma16816(cQQ[2*nb+1], fQh, bl4[2], bl4[3]);
        }
        __syncthreads();
    }

    const size_t pb = (size_t)(bh * CH2_ + c) * R_ * R_;
    const int m0 = warp * 16 + g;
    #pragma unroll
    for (int nb = 0; nb < 8; nb++) {
        const int col = nb * 8 + tg * 2;
        *(float2*)&g_pKV[pb + (size_t)m0 * 64 + col]       = make_float2(cKV[nb][0], cKV[nb][1]);
        *(float2*)&g_pKV[pb + (size_t)(m0 + 8) * 64 + col] = make_float2(cKV[nb][2], cKV[nb][3]);
        *(float2*)&g_pKK[pb + (size_t)m0 * 64 + col]       = make_float2(cKK[nb][0], cKK[nb][1]);
        *(float2*)&g_pKK[pb + (size_t)(m0 + 8) * 64 + col] = make_float2(cKK[nb][2], cKK[nb][3]);
        *(float2*)&g_pQQ[pb + (size_t)m0 * 64 + col]       = make_float2(cQQ[nb][0], cQQ[nb][1]);
        *(float2*)&g_pQQ[pb + (size_t)(m0 + 8) * 64 + col] = make_float2(cQQ[nb][2], cQQ[nb][3]);
    }
}

// ============================================================================
// R1: reduce chunk partials. grid (32, 16), 64 threads — 512 blocks.
// ============================================================================
__global__ void __launch_bounds__(64) svda_r1() {
    const int bh = blockIdx.x, eb = blockIdx.y;
    const int tid = threadIdx.x;
    const int e = (eb * 64 + tid) * 4;
    float4 kv = make_float4(0.f,0.f,0.f,0.f), kk = kv, qq = kv;
    #pragma unroll
    for (int cc = 0; cc < CH2_; cc++) {
        const size_t o = (size_t)(bh * CH2_ + cc) * R_ * R_ + e;
        const float4 a = *(const float4*)&g_pKV[o];
        const float4 d = *(const float4*)&g_pKK[o];
        const float4 q = *(const float4*)&g_pQQ[o];
        kv.x += a.x; kv.y += a.y; kv.z += a.z; kv.w += a.w;
        kk.x += d.x; kk.y += d.y; kk.z += d.z; kk.w += d.w;
        qq.x += q.x; qq.y += q.y; qq.z += q.z; qq.w += q.w;
    }
    *(float4*)&g_KtV[(size_t)bh * R_ * R_ + e] = kv;
    const int i = e >> 6, j0 = e & 63;
    float dg[4] = {0.f, 0.f, 0.f, 0.f};
    if (i >= j0 && i < j0 + 4) dg[i - j0] = 1.0f;
    float aQ = fabsf(qq.x - dg[0]) + fabsf(qq.y - dg[1]) + fabsf(qq.z - dg[2]) + fabsf(qq.w - dg[3]);
    float aK = fabsf(kk.x - dg[0]) + fabsf(kk.y - dg[1]) + fabsf(kk.z - dg[2]) + fabsf(kk.w - dg[3]);

    __shared__ float rQ[64], rK[64];
    rQ[tid] = aQ; rK[tid] = aK;
    __syncthreads();
    for (int st = 32; st > 0; st >>= 1) {
        if (tid < st) { rQ[tid] += rQ[tid + st]; rK[tid] += rK[tid + st]; }
        __syncthreads();
    }
    if (tid == 0) { g_sQp[bh * EB_ + eb] = rQ[0]; g_sKp[bh * EB_ + eb] = rK[0]; }
}

// ============================================================================
// R2: finalize ortho_loss[b]
// ============================================================================
__global__ void svda_r2(float* __restrict__ out) {
    const int tid = threadIdx.x;
    __shared__ float sm[BH_];
    if (tid < BH_) {
        float s = 0.0f;
        #pragma unroll
        for (int eb = 0; eb < EB_; eb++)
            s += g_sQp[tid * EB_ + eb] + g_sKp[tid * EB_ + eb];
        sm[tid] = s;
    }
    __syncthreads();
    if (tid < B_) {
        float s = 0.0f;
        #pragma unroll
        for (int h = 0; h < H_; h++) s += sm[tid * H_ + h];
        out[(size_t)BH_ * N_ * R_ + tid] = 0.1f * s / (float)(H_ * R_ * R_);
    }
}

// ============================================================================
// K3 (HMMA): X[128x64] = Qf[128x64] @ KtV[64x64] per (bh, cb). 128 threads.
// A = Qf row-major [n][r] via ldmatrix (non-trans); B = KtV [r][d] via
// ldmatrix.trans — same addressing pattern hardware-validated in k2.
// bf16 hi/lo split, 3 products, fp32 accum. Warp w owns rows 32w..32w+31.
// smem (bf16 elems): Qh[128*72] Ql Kh[64*72] Kl + filt(f32)
// ============================================================================
#define K3P_ 72
#define K3_QH 0
#define K3_QL (128*K3P_)
#define K3_KH (2*128*K3P_)
#define K3_KL (2*128*K3P_ + 64*K3P_)
#define K3_FILT (2*128*K3P_ + 2*64*K3P_)
#define K3SMEM_ ((K3_FILT)*2 + 256)

__global__ void __launch_bounds__(128) svda_k3(const float* __restrict__ U,
                                               const float* __restrict__ Sigma,
                                               const float* __restrict__ gammas,
                                               int ng,
                                               float* __restrict__ X) {
    extern __shared__ __align__(16) unsigned short s3[];
    unsigned short* Qh = s3 + K3_QH;
    unsigned short* Ql = s3 + K3_QL;
    unsigned short* Kh = s3 + K3_KH;
    unsigned short* Kl = s3 + K3_KL;
    float* filt = (float*)(s3 + K3_FILT);

    const int bh = blockIdx.x, cb = blockIdx.y;
    const int tid = threadIdx.x, warp = tid >> 5, lane = tid & 31;
    const int g = lane >> 2, tg = lane & 3;

    // filt + KtV hi/lo split (tid < 64: one KtV row each)
    if (tid < 64) {
        const float x  = Sigma[bh * R_ + tid];
        const float sg = 1.0f / (1.0f + __expf(-x));
        float o = gammas[ng - 1];
        for (int k = ng - 2; k >= 0; k--) o = fmaf(o, sg, gammas[k]);
        filt[tid] = o;

        const float* kr = g_KtV + (size_t)bh * R_ * R_ + (size_t)tid * R_;
        const int ro = tid * K3P_;
        #pragma unroll
        for (int q = 0; q < 8; q++) {
            const float4 aa = *(const float4*)&kr[q * 8];
            const float4 bb = *(const float4*)&kr[q * 8 + 4];
            u32 h0, l0, h1, l1, h2, l2, h3, l3;
            split2(aa.x, aa.y, h0, l0); split2(aa.z, aa.w, h1, l1);
            split2(bb.x, bb.y, h2, l2); split2(bb.z, bb.w, h3, l3);
            *(uint4*)&Kh[ro + q * 8] = make_uint4(h0, h1, h2, h3);
            *(uint4*)&Kl[ro + q * 8] = make_uint4(l0, l1, l2, l3);
        }
    }

    // Qf softmax (thread per row, no smem dependency yet)
    float u[64];
    {
        const float* ur = U + ((size_t)bh * N_ + (size_t)cb * 128 + tid) * R_;
        #pragma unroll
        for (int q = 0; q < 16; q++) {
            const float4 t4 = *(const float4*)(ur + q * 4);
            u[q*4+0] = t4.x; u[q*4+1] = t4.y; u[q*4+2] = t4.z; u[q*4+3] = t4.w;
        }
        float mx = u[0];
        #pragma unroll
        for (int r = 1; r < 64; r++) mx = fmaxf(mx, u[r]);
        float sm = 0.0f;
        #pragma unroll
        for (int r = 0; r < 64; r++) { u[r] = __expf(u[r] - mx); sm += u[r]; }
        const float inv = 1.0f / sm;
        #pragma unroll
        for (int r = 0; r < 64; r++) u[r] *= inv;
    }
    __syncthreads();   // filt ready

    // scale by filt, split to bf16 hi/lo, store row-major [n][r]
    {
        const int ro = tid * K3P_;
        #pragma unroll
        for (int q = 0; q < 8; q++) {
            const float4 f0 = *(const float4*)&filt[q * 8];
            const float4 f1 = *(const float4*)&filt[q * 8 + 4];
            u32 h0, l0, h1, l1, h2, l2, h3, l3;
            split2(u[q*8+0]*f0.x, u[q*8+1]*f0.y, h0, l0);
            split2(u[q*8+2]*f0.z, u[q*8+3]*f0.w, h1, l1);
            split2(u[q*8+4]*f1.x, u[q*8+5]*f1.y, h2, l2);
            split2(u[q*8+6]*f1.z, u[q*8+7]*f1.w, h3, l3);
            *(uint4*)&Qh[ro + q * 8] = make_uint4(h0, h1, h2, h3);
            *(uint4*)&Ql[ro + q * 8] = make_uint4(l0, l1, l2, l3);
        }
    }
    __syncthreads();

    // ---- HMMA: warp w owns m-rows 32w..32w+31 ----
    // A (non-trans) lane map: row = (lane&7) + ((lane>>3)&1)*8 ; col = ((lane>>4)&1)*8
    const int ar = (lane & 7) + ((lane >> 3) & 1) * 8;
    const int ac = ((lane >> 4) & 1) * 8;
    // B (trans) lane map: row = (lane&7) + ((lane>>3)&1)*8 ; col = ((lane>>4)&1)*8
    const u32 qbase = (u32)__cvta_generic_to_shared(Qh);
    const u32 aoffH = qbase + (u32)((warp * 32 + ar) * K3P_ + ac) * 2;
    const u32 aoffL = aoffH + (u32)(128 * K3P_) * 2;
    const u32 kbase = (u32)__cvta_generic_to_shared(Kh);
    const u32 boffH = kbase + (u32)(ar * K3P_ + ac) * 2;
    const u32 boffL = boffH + (u32)(64 * K3P_) * 2;

    float c[2][8][4];
    #pragma unroll
    for (int mt = 0; mt < 2; mt++)
        #pragma unroll
        for (int nb = 0; nb < 8; nb++)
            #pragma unroll
            for (int j = 0; j < 4; j++) c[mt][nb][j] = 0.f;

    #pragma unroll
    for (int ks = 0; ks < 4; ks++) {
        u32 fh[2][4], fl[2][4];
        ldm4(aoffH + (u32)(ks * 16) * 2, fh[0]);
        ldm4(aoffH + (u32)(16 * K3P_ + ks * 16) * 2, fh[1]);
        ldm4(aoffL + (u32)(ks * 16) * 2, fl[0]);
        ldm4(aoffL + (u32)(16 * K3P_ + ks * 16) * 2, fl[1]);
        #pragma unroll
        for (int nq = 0; nq < 4; nq++) {
            u32 bh4[4], bl4[4];
            ldmT4(boffH + (u32)(ks * 16 * K3P_ + nq * 16) * 2, bh4);
            ldmT4(boffL + (u32)(ks * 16 * K3P_ + nq * 16) * 2, bl4);
            #pragma unroll
            for (int mt = 0; mt < 2; mt++) {
                mma16816(c[mt][2*nq],   fh[mt], bh4[0], bh4[1]);
                mma16816(c[mt][2*nq+1], fh[mt], bh4[2], bh4[3]);
                mma16816(c[mt][2*nq],   fl[mt], bh4[0], bh4[1]);
                mma16816(c[mt][2*nq+1], fl[mt], bh4[2], bh4[3]);
                mma16816(c[mt][2*nq],   fh[mt], bl4[0], bl4[1]);
                mma16816(c[mt][2*nq+1], fh[mt], bl4[2], bl4[3]);
            }
        }
    }

    // epilogue
    const size_t rbase = (size_t)bh * N_ + (size_t)cb * 128 + warp * 32;
    #pragma unroll
    for (int mt = 0; mt < 2; mt++) {
        const size_t r0 = rbase + mt * 16 + g;
        #pragma unroll
        for (int nb = 0; nb < 8; nb++) {
            const int col = nb * 8 + tg * 2;
            *(float2*)&X[(r0)     * R_ + col] = make_float2(c[mt][nb][0], c[mt][nb][1]);
            *(float2*)&X[(r0 + 8) * R_ + col] = make_float2(c[mt][nb][2], c[mt][nb][3]);
        }
    }
}

// ============================================================================
// launcher
// ============================================================================
extern "C" void kernel_launch(void* const* d_in, const int* in_sizes, int n_in,
                              void* d_out, int out_size) {
    const float* U      = (const float*)d_in[0];
    const float* Sigma  = (const float*)d_in[1];
    const float* svd_V  = (const float*)d_in[2];
    const float* V      = (const float*)d_in[3];
    const float* mask   = (const float*)d_in[4];
    const float* gammas = (const float*)d_in[5];
    const int ng = in_sizes[5];
    float* out = (float*)d_out;

    cudaFuncSetAttribute(svda_k3, cudaFuncAttributeMaxDynamicSharedMemorySize, K3SMEM_);

    svda_ks1<<<dim3(BH_, KCH_), 256>>>(svd_V, mask);
    svda_ks2<<<BH_, 64>>>();
    svda_k2 <<<dim3(BH_, CH2_), 128>>>(U, svd_V, V, mask);
    svda_r1 <<<dim3(BH_, EB_), 64>>>();
    svda_r2 <<<1, 32>>>(out);
    svda_k3 <<<dim3(BH_, N_ / 128), 128, K3SMEM_>>>(U, Sigma, gammas, ng, out);
}